// round 15
// baseline (speedup 1.0000x reference)
#include <cuda_runtime.h>
#include <cuda_bf16.h>
#include <cuda_fp16.h>
#include <cstdint>

#define NMAX 524288
#define E 8
#define H 64
#define STPB 512
#define MTPB 256
#define BPE 37
#define CAP 73728   // fixed per-expert bucket capacity (mean 65536 + 34 sigma)

// ---- scratch ----
__device__ uint4 g_xs[E * CAP];       // staged: (pack(xn0,xn1), pack(xn2,1), p, 0)
__device__ int g_cursor[E] = {0, CAP, 2 * CAP, 3 * CAP,
                              4 * CAP, 5 * CAP, 6 * CAP, 7 * CAP};
__device__ int g_done = 0;

// ================= helpers =================
__device__ __forceinline__ uint32_t packh2(float lo, float hi) {
    uint32_t r;
    asm("cvt.rn.f16x2.f32 %0, %1, %2;" : "=r"(r) : "f"(hi), "f"(lo));
    return r;
}

__device__ __forceinline__ void mma16816(float* c, const uint32_t* a,
                                         uint32_t b0, uint32_t b1) {
    asm volatile(
        "mma.sync.aligned.m16n8k16.row.col.f32.f16.f16.f32 "
        "{%0,%1,%2,%3}, {%4,%5,%6,%7}, {%8,%9}, {%0,%1,%2,%3};"
        : "+f"(c[0]), "+f"(c[1]), "+f"(c[2]), "+f"(c[3])
        : "r"(a[0]), "r"(a[1]), "r"(a[2]), "r"(a[3]), "r"(b0), "r"(b1));
}

// layer-1 MMA with fp16 accumulator: output regs are packed fp16 pairs in
// exactly the layer-2 A-fragment layout. Only k rows 0..3 nonzero.
__device__ __forceinline__ void mma16816_h_k4(uint32_t* d, uint32_t a0,
                                              uint32_t a1, uint32_t b0) {
    uint32_t z = 0;
    asm volatile(
        "mma.sync.aligned.m16n8k16.row.col.f16.f16.f16.f16 "
        "{%0,%1}, {%2,%3,%4,%5}, {%6,%7}, {%8,%9};"
        : "=r"(d[0]), "=r"(d[1])
        : "r"(a0), "r"(a1), "r"(z), "r"(z), "r"(b0), "r"(z), "r"(z), "r"(z));
}

__device__ __forceinline__ uint32_t relu2(uint32_t v) {
    __half2 h = *reinterpret_cast<__half2*>(&v);
    __half2 r = __hmax2(h, __half2half2(__ushort_as_half(0)));
    return *reinterpret_cast<uint32_t*>(&r);
}

__device__ __forceinline__ int route_idx(float x0, float x1, float x2) {
    float u0 = fminf(fmaxf((x0 + 1.0f) * 0.5f, 0.0f), 0.99f);
    float u1 = fminf(fmaxf((x1 + 1.0f) * 0.5f, 0.0f), 0.99f);
    float u2 = fminf(fmaxf((x2 + 1.0f) * 0.5f, 0.0f), 0.99f);
    return (int)(u0 * 2.0f) + 2 * (int)(u1 * 2.0f) + 4 * (int)(u2 * 2.0f);
}

// ================= fused route+normalize+scatter =================
__global__ void k_scatter(const float* __restrict__ x,
                          const float* __restrict__ emin_g,
                          const float* __restrict__ emax_g, int n) {
    __shared__ int hist[E], sbase[E], scur[E];
    __shared__ float sex[E * 6];
    int tid = threadIdx.x;
    if (tid < E) { hist[tid] = 0; scur[tid] = 0; }
    if (tid < E * 3) {
        int e = tid / 3, c = tid % 3;
        sex[e * 6 + c]     = emin_g[tid];
        sex[e * 6 + 3 + c] = emax_g[tid];
    }
    __syncthreads();
    int i = blockIdx.x * STPB + tid;
    int e = 0;
    float x0 = 0.f, x1 = 0.f, x2 = 0.f;
    if (i < n) {
        x0 = x[3 * i + 0];
        x1 = x[3 * i + 1];
        x2 = x[3 * i + 2];
        e = route_idx(x0, x1, x2);
        atomicAdd(&hist[e], 1);
    }
    __syncthreads();
    if (tid < E) sbase[tid] = atomicAdd(&g_cursor[tid], hist[tid]);
    __syncthreads();
    if (i < n) {
        int r = atomicAdd(&scur[e], 1);
        float mn0 = sex[e * 6 + 0], mx0 = sex[e * 6 + 3];
        float mn1 = sex[e * 6 + 1], mx1 = sex[e * 6 + 4];
        float mn2 = sex[e * 6 + 2], mx2 = sex[e * 6 + 5];
        float xn0 = -1.0f + 2.0f * (x0 - mn0) / (mx0 - mn0);
        float xn1 = -1.0f + 2.0f * (x1 - mn1) / (mx1 - mn1);
        float xn2 = -1.0f + 2.0f * (x2 - mn2) / (mx2 - mn2);
        g_xs[sbase[e] + r] = make_uint4(packh2(xn0, xn1), packh2(xn2, 1.0f),
                                        (uint32_t)i, 0u);
    }
}

// ================= HMMA MLP =================
// Warp tile: M=32 points. Both layers on tensor cores, single-pass fp16.
// Layer 1: fp16-accum k4-MMAs whose packed C regs ARE the layer-2 A frags.
// Layer 2: 64 f32-accum MMAs, nt-halves of 4, fused epilogue. The last
// finishing block resets g_cursor/g_done for the next graph replay.
__global__ void __launch_bounds__(MTPB, 2)
k_mlp(const float* __restrict__ W1g, const float* __restrict__ b1g,
      const float* __restrict__ W2g, const float* __restrict__ b2g,
      const float* __restrict__ W3g, const float* __restrict__ b3g,
      float* __restrict__ out) {
    __shared__ uint2 sB2[4][8][32];   // layer-2 B frags [kt][nt][lane]
    __shared__ uint32_t sB1[8][32];   // layer-1 B frags [nt][lane]
    __shared__ float4 sEW[32];        // [nt*4+c4] = (b2[n0], b2[n0+1], W3[n0], W3[n0+1])
    __shared__ float sb3v;

    const int tid = threadIdx.x;
    const int e  = blockIdx.x / BPE;
    const int jb = blockIdx.x % BPE;

    // read cursor FIRST (reset ordering depends on read-before-done-increment)
    const int gb  = e * CAP;
    const int cnt = g_cursor[e] - gb;

    // ---- stage layer-1 B fragments: W1' rows = [W1[0], W1[1], W1[2], b1, 0..] ----
    if (tid < 256) {
        int nt = tid >> 5, ln = tid & 31;
        int sel = ln & 3;
        int n = nt * 8 + (ln >> 2);
        uint32_t v = 0;
        if (sel == 0) v = packh2(W1g[e * 3 * H + 0 * H + n], W1g[e * 3 * H + 1 * H + n]);
        else if (sel == 1) v = packh2(W1g[e * 3 * H + 2 * H + n], b1g[e * H + n]);
        sB1[nt][ln] = v;
    }
    if (tid < 32) {
        int nt = tid >> 2, c4v = tid & 3;
        int n0 = nt * 8 + 2 * c4v;
        sEW[tid] = make_float4(b2g[e * H + n0], b2g[e * H + n0 + 1],
                               W3g[e * H + n0], W3g[e * H + n0 + 1]);
    }
    if (tid == 0) sb3v = b3g[e];

    // ---- stage layer-2 B fragments (W2 fp16, mma order) ----
    {
        const float* w2e = W2g + e * H * H;
        for (int it = 0; it < 4; it++) {
            int idx = tid + it * MTPB;
            int kt = idx >> 8;
            int nt = (idx >> 5) & 7;
            int ln = idx & 31;
            int k0 = kt * 16 + 2 * (ln & 3);
            int n  = nt * 8 + (ln >> 2);
            sB2[kt][nt][ln] = make_uint2(
                packh2(w2e[(k0)     * H + n], w2e[(k0 + 1) * H + n]),
                packh2(w2e[(k0 + 8) * H + n], w2e[(k0 + 9) * H + n]));
        }
    }
    __syncthreads();

    const int lane = tid & 31;
    const int wid  = tid >> 5;
    const int c4 = lane & 3;
    const int r4 = lane >> 2;
    const float b3s = sb3v;

    const int stride = BPE * 8 * 32;
    const int base0 = (jb * 8 + wid) * 32;

    if (cnt > 0) {
        // prefetch first tile's record
        uint4 q;
        if (base0 < cnt) q = g_xs[gb + min(base0 + lane, cnt - 1)];

        for (int base = base0; base < cnt; base += stride) {
            // prefetch next tile early (hides LDG latency behind MMA work)
            uint4 qn;
            int nb = base + stride;
            if (nb < cnt) qn = g_xs[gb + min(nb + lane, cnt - 1)];

            uint32_t pa = q.x, pb = q.y;
            int p = (int)q.z;

            // ---- gather packed A' rows for this thread's fragment rows ----
            uint32_t av[4];
#pragma unroll
            for (int rs = 0; rs < 4; rs++) {
                int src = r4 + 8 * rs;
                uint32_t va = __shfl_sync(0xffffffffu, pa, src);
                uint32_t vb = __shfl_sync(0xffffffffu, pb, src);
                av[rs] = (c4 == 0) ? va : ((c4 == 1) ? vb : 0u);
            }

            // ---- layer 1: fp16-accum MMAs, relu2 straight into A frags ----
            uint32_t af[4][2][4];
#pragma unroll
            for (int nt = 0; nt < 8; nt++) {
                int kt = nt >> 1;
                int hi = (nt & 1) * 2;
#pragma unroll
                for (int mt = 0; mt < 2; mt++) {
                    uint32_t d[2];
                    mma16816_h_k4(d, av[2 * mt], av[2 * mt + 1], sB1[nt][lane]);
                    af[kt][mt][hi + 0] = relu2(d[0]);
                    af[kt][mt][hi + 1] = relu2(d[1]);
                }
            }

            // ---- layer 2: nt in halves of 4, kt inner, fused epilogue ----
            float acc[4] = {0.0f, 0.0f, 0.0f, 0.0f};
#pragma unroll
            for (int hn = 0; hn < 2; hn++) {
                float C[2][4][4];
#pragma unroll
                for (int mt = 0; mt < 2; mt++)
#pragma unroll
                    for (int ntl = 0; ntl < 4; ntl++)
#pragma unroll
                        for (int qq = 0; qq < 4; qq++) C[mt][ntl][qq] = 0.0f;

#pragma unroll
                for (int kt = 0; kt < 4; kt++) {
                    uint2 bq[4];
#pragma unroll
                    for (int ntl = 0; ntl < 4; ntl++)
                        bq[ntl] = sB2[kt][hn * 4 + ntl][lane];
#pragma unroll
                    for (int ntl = 0; ntl < 4; ntl++) {
                        mma16816(C[0][ntl], af[kt][0], bq[ntl].x, bq[ntl].y);
                        mma16816(C[1][ntl], af[kt][1], bq[ntl].x, bq[ntl].y);
                    }
                }

#pragma unroll
                for (int ntl = 0; ntl < 4; ntl++) {
                    int nt = hn * 4 + ntl;
                    float4 ew = sEW[nt * 4 + c4];
#pragma unroll
                    for (int mt = 0; mt < 2; mt++)
#pragma unroll
                        for (int half = 0; half < 2; half++) {
                            int rs = 2 * mt + half;
                            float v0 = C[mt][ntl][half * 2 + 0] + ew.x;
                            float v1 = C[mt][ntl][half * 2 + 1] + ew.y;
                            acc[rs] = fmaf(fmaxf(v0, 0.0f), ew.z, acc[rs]);
                            acc[rs] = fmaf(fmaxf(v1, 0.0f), ew.w, acc[rs]);
                        }
                }
            }

            // ---- reduce across the 4-lane n-group, store ----
#pragma unroll
            for (int rs = 0; rs < 4; rs++) {
                float a = acc[rs];
                a += __shfl_xor_sync(0xffffffffu, a, 1);
                a += __shfl_xor_sync(0xffffffffu, a, 2);
                int row = r4 + 8 * rs;
                int pr = __shfl_sync(0xffffffffu, p, row);
                if (c4 == 0 && base + row < cnt) out[pr] = a + b3s;
            }

            q = qn;
        }
    }

    // ---- last-finishing block resets cursors for the next graph replay ----
    __syncthreads();
    if (tid == 0) {
        __threadfence();
        int d = atomicAdd(&g_done, 1);
        if (d == (int)gridDim.x - 1) {
            g_done = 0;
#pragma unroll
            for (int ee = 0; ee < E; ee++) g_cursor[ee] = ee * CAP;
            __threadfence();
        }
    }
}

extern "C" void kernel_launch(void* const* d_in, const int* in_sizes, int n_in,
                              void* d_out, int out_size) {
    const float* x    = (const float*)d_in[0];
    const float* emin = (const float*)d_in[1];
    const float* emax = (const float*)d_in[2];
    const float* W1   = (const float*)d_in[3];
    const float* b1   = (const float*)d_in[4];
    const float* W2   = (const float*)d_in[5];
    const float* b2   = (const float*)d_in[6];
    const float* W3   = (const float*)d_in[7];
    const float* b3   = (const float*)d_in[8];
    float* out = (float*)d_out;

    int n = in_sizes[0] / 3;
    int nblk = (n + STPB - 1) / STPB;

    k_scatter<<<nblk, STPB>>>(x, emin, emax, n);
    k_mlp<<<E * BPE, MTPB>>>(W1, b1, W2, b2, W3, b3, out);
}